// round 1
// baseline (speedup 1.0000x reference)
#include <cuda_runtime.h>
#include <cuda_bf16.h>
#include <cstdint>

// Problem constants
#define BB   8
#define CC   64
#define NN   4096
#define OO   128
#define KNN  20

// KNN kernel tiling
#define TI   128      // i rows per block
#define TJ   128      // j cols per chunk
#define SCRP 132      // scr row pitch (floats), %4==0 for float4, stride-4-bank

// ---------------- scratch (static device globals; no allocation) -------------
__device__ float g_xx[BB * NN];                 // ||x_j||^2 per point
__device__ float g_Ut[CC * 256];                // combined weights, [c][o'] o'=0..255
__device__ float g_GT[(size_t)BB * NN * OO];    // G^T: [b][j][o], o contiguous
__device__ float g_HT[(size_t)BB * NN * OO];    // H^T: [b][i][o] (incl. bias)
__device__ int   g_idx[(size_t)BB * NN * KNN];  // knn indices

// ---------------- kernel 1: xx[b][j] = sum_c x[b][c][j]^2 --------------------
__global__ void xx_kernel(const float* __restrict__ x) {
    int b = blockIdx.y;
    int j = blockIdx.x * 256 + threadIdx.x;
    const float* xb = x + (size_t)b * CC * NN;
    float acc = 0.f;
#pragma unroll
    for (int c = 0; c < CC; ++c) {
        float v = xb[c * NN + j];
        acc += v * v;
    }
    g_xx[b * NN + j] = acc;
}

// ---------------- kernel 2: build combined weight Ut[c][o'] ------------------
// o' < 128 : w1[o'][c] = W[o'][c]
// o' >=128 : (w2 - w1)[o'-128][c] = W[o'-128][CC+c] - W[o'-128][c]
__global__ void uprep_kernel(const float* __restrict__ W) {
    int c = blockIdx.x;          // 0..63
    int o = threadIdx.x;         // 0..255
    float v;
    if (o < OO) v = W[o * (2 * CC) + c];
    else {
        int oo = o - OO;
        v = W[oo * (2 * CC) + CC + c] - W[oo * (2 * CC) + c];
    }
    g_Ut[c * 256 + o] = v;
}

// ---------------- kernel 3: GH^T = Ut^T-GEMM -> g_GT / g_HT ------------------
// Per block: 256 o' x 64 j tile, K = 64.  grid (NN/64, BB), 256 threads.
// smem: su[64][256] (64KB) + sx[64][64] (16KB) = 80KB dynamic.
__global__ __launch_bounds__(256) void gemm_gh_kernel(const float* __restrict__ x,
                                                      const float* __restrict__ bvec) {
    extern __shared__ float sm[];
    float* su = sm;                 // [64][256]
    float* sx = sm + CC * 256;      // [64][64]

    int b = blockIdx.y;
    int jbase = blockIdx.x * 64;
    int t = threadIdx.x;
    int tx = t & 7;                 // j group (8 j's)
    int ty = t >> 3;                // o group (8 o's), 0..31

    // load Ut (already [c][o'] layout) : 16384 floats = 4096 float4
    const float4* ut4 = (const float4*)g_Ut;
    float4* su4 = (float4*)su;
    for (int k = t; k < CC * 256 / 4; k += 256) su4[k] = ut4[k];

    // load x tile [c][jj] : 64x64
    const float* xb = x + (size_t)b * CC * NN;
    for (int k = t; k < CC * 16; k += 256) {
        int c = k >> 4, p = k & 15;
        float4 v = *(const float4*)&xb[c * NN + jbase + p * 4];
        *(float4*)&sx[c * 64 + p * 4] = v;
    }
    __syncthreads();

    float acc[8][8];
#pragma unroll
    for (int i = 0; i < 8; ++i)
#pragma unroll
        for (int j = 0; j < 8; ++j) acc[i][j] = 0.f;

#pragma unroll 4
    for (int c = 0; c < CC; ++c) {
        float4 a0 = *(float4*)&su[c * 256 + ty * 8];
        float4 a1 = *(float4*)&su[c * 256 + ty * 8 + 4];
        float4 b0 = *(float4*)&sx[c * 64 + tx * 8];
        float4 b1 = *(float4*)&sx[c * 64 + tx * 8 + 4];
        float aa[8] = {a0.x, a0.y, a0.z, a0.w, a1.x, a1.y, a1.z, a1.w};
        float bb[8] = {b0.x, b0.y, b0.z, b0.w, b1.x, b1.y, b1.z, b1.w};
#pragma unroll
        for (int i = 0; i < 8; ++i)
#pragma unroll
            for (int j = 0; j < 8; ++j) acc[i][j] += aa[i] * bb[j];
    }

    // epilogue: o' rows 0..127 -> GT[b][j][o]; rows 128..255 -> HT[b][j][o-128]+bias
    int obase = ty * 8;
    bool isH = (obase >= OO);
    float bias[8];
    if (isH) {
#pragma unroll
        for (int i = 0; i < 8; ++i) bias[i] = bvec[obase - OO + i];
    }
#pragma unroll
    for (int jq = 0; jq < 8; ++jq) {
        int j = jbase + tx * 8 + jq;
        float* dst = isH ? &g_HT[((size_t)b * NN + j) * OO + (obase - OO)]
                         : &g_GT[((size_t)b * NN + j) * OO + obase];
#pragma unroll
        for (int i = 0; i < 8; ++i) {
            float v = acc[i][jq];
            if (isH) v += bias[i];
            dst[i] = v;
        }
    }
}

// ---------------- kernel 4: fused distance GEMM + streaming top-20 -----------
// grid (NN/TI, BB), 256 threads, dynamic smem ~150.5KB.
__global__ __launch_bounds__(256) void knn_kernel(const float* __restrict__ x) {
    extern __shared__ float sm[];
    float* si   = sm;                          // [64][128]  32KB
    float* sj   = si + CC * TI;                // [64][128]  32KB
    float* sxxj = sj + CC * TJ;                // [128]
    float* scr  = sxxj + TJ;                   // [128][132] 67.6KB
    float* lv   = scr + TI * SCRP;             // [128][20]
    int*   li   = (int*)(lv + TI * KNN);       // [128][20]

    int b = blockIdx.y;
    int ibase = blockIdx.x * TI;
    int t = threadIdx.x;
    int tx = t & 15;                           // j group
    int ty = t >> 4;                           // i group

    const float* xb = x + (size_t)b * CC * NN;
    const float* xxb = g_xx + b * NN;

    // init top-k lists
    for (int k = t; k < TI * KNN; k += 256) { lv[k] = -3.4e38f; li[k] = 0; }

    // load si (i tile), once
    for (int k = t; k < CC * 32; k += 256) {
        int c = k >> 5, p = k & 31;
        float4 v = *(const float4*)&xb[c * NN + ibase + p * 4];
        *(float4*)&si[c * TI + p * 4] = v;
    }
    // (no barrier needed yet; first chunk loop starts with loads then barrier)

    for (int jbase = 0; jbase < NN; jbase += TJ) {
        // load j tile + xx chunk (all 256 threads)
        for (int k = t; k < CC * 32; k += 256) {
            int c = k >> 5, p = k & 31;
            float4 v = *(const float4*)&xb[c * NN + jbase + p * 4];
            *(float4*)&sj[c * TJ + p * 4] = v;
        }
        if (t < 32) {
            float4 v = *(const float4*)&xxb[jbase + t * 4];
            *(float4*)&sxxj[t * 4] = v;
        }
        __syncthreads();   // joins: loads done AND previous merge done (merge warps arrive here)

        float acc[8][8];
#pragma unroll
        for (int i = 0; i < 8; ++i)
#pragma unroll
            for (int j = 0; j < 8; ++j) acc[i][j] = 0.f;

#pragma unroll 4
        for (int c = 0; c < CC; ++c) {
            float4 a0 = *(float4*)&si[c * TI + ty * 8];
            float4 a1 = *(float4*)&si[c * TI + ty * 8 + 4];
            float4 b0 = *(float4*)&sj[c * TJ + tx * 8];
            float4 b1 = *(float4*)&sj[c * TJ + tx * 8 + 4];
            float aa[8] = {a0.x, a0.y, a0.z, a0.w, a1.x, a1.y, a1.z, a1.w};
            float bb[8] = {b0.x, b0.y, b0.z, b0.w, b1.x, b1.y, b1.z, b1.w};
#pragma unroll
            for (int i = 0; i < 8; ++i)
#pragma unroll
                for (int j = 0; j < 8; ++j) acc[i][j] += aa[i] * bb[j];
        }

        // score = 2*dot - xx_j  (drop -xx_i: constant per row, rank-invariant)
#pragma unroll
        for (int i = 0; i < 8; ++i) {
            int r = ty * 8 + i;
#pragma unroll
            for (int j = 0; j < 8; ++j) {
                int jj = tx * 8 + j;
                scr[r * SCRP + jj] = 2.f * acc[i][j] - sxxj[jj];
            }
        }
        __syncthreads();   // scores visible before merge

        // streaming top-20 merge: thread r owns row r (threads 128..255 idle ->
        // they loop around and prefetch next sj while warps 0-3 merge)
        if (t < TI) {
            float* lvr = lv + t * KNN;
            int*   lir = li + t * KNN;
            float thr = lvr[KNN - 1];
            const float* srow = scr + t * SCRP;
#pragma unroll 4
            for (int jj = 0; jj < TJ; jj += 4) {
                float4 v = *(const float4*)&srow[jj];
                float vs[4] = {v.x, v.y, v.z, v.w};
#pragma unroll
                for (int q = 0; q < 4; ++q) {
                    float s = vs[q];
                    if (s > thr) {
                        int p = KNN - 1;
                        while (p > 0 && lvr[p - 1] < s) {
                            lvr[p] = lvr[p - 1];
                            lir[p] = lir[p - 1];
                            --p;
                        }
                        lvr[p] = s;
                        lir[p] = jbase + jj + q;
                        thr = lvr[KNN - 1];
                    }
                }
            }
        }
        // no barrier here: non-merge threads may start next chunk's sj load
        // (merge never touches sj; the top-of-loop barrier re-joins everyone)
    }
    __syncthreads();

    if (t < TI) {
        int* dst = &g_idx[((size_t)b * NN + ibase + t) * KNN];
#pragma unroll
        for (int k = 0; k < KNN; ++k) dst[k] = li[t * KNN + k];
    }
}

// ---------------- kernel 5: gather-max + leaky + transposed write ------------
// grid (NN/32, BB), 256 threads (8 warps x 4 points), smem idx + result tile.
__global__ __launch_bounds__(256) void gathermax_kernel(float* __restrict__ out) {
    __shared__ int   sidx[32 * KNN];
    __shared__ float sres[32 * SCRP / 4 * 4]; // 32 rows pitch 132 -> use below
    int b = blockIdx.y;
    int ibase = blockIdx.x * 32;
    int t = threadIdx.x;
    int w = t >> 5;    // warp 0..7
    int l = t & 31;    // lane

    // load indices for 32 points
    for (int k = t; k < 32 * KNN; k += 256)
        sidx[k] = g_idx[((size_t)b * NN + ibase) * KNN + k];
    __syncthreads();

    const float* GTb = g_GT + (size_t)b * NN * OO;
    const float* HTb = g_HT + (size_t)b * NN * OO;

#pragma unroll
    for (int p = 0; p < 4; ++p) {
        int pp = w * 4 + p;                 // local point 0..31
        int i = ibase + pp;
        float4 m = make_float4(-3.4e38f, -3.4e38f, -3.4e38f, -3.4e38f);
#pragma unroll
        for (int k = 0; k < KNN; ++k) {
            int j = sidx[pp * KNN + k];
            float4 g = *(const float4*)&GTb[(size_t)j * OO + l * 4];
            m.x = fmaxf(m.x, g.x); m.y = fmaxf(m.y, g.y);
            m.z = fmaxf(m.z, g.z); m.w = fmaxf(m.w, g.w);
        }
        float4 h = *(const float4*)&HTb[(size_t)i * OO + l * 4];
        float v0 = m.x + h.x, v1 = m.y + h.y, v2 = m.z + h.z, v3 = m.w + h.w;
        v0 = v0 >= 0.f ? v0 : 0.2f * v0;
        v1 = v1 >= 0.f ? v1 : 0.2f * v1;
        v2 = v2 >= 0.f ? v2 : 0.2f * v2;
        v3 = v3 >= 0.f ? v3 : 0.2f * v3;
        *(float4*)&sres[pp * SCRP + l * 4] = make_float4(v0, v1, v2, v3);
    }
    __syncthreads();

    // transposed coalesced write: out[b][o][ibase+ii]
    float* ob = out + (size_t)b * OO * NN;
    for (int k = t; k < OO * 32; k += 256) {
        int o = k >> 5, ii = k & 31;
        ob[(size_t)o * NN + ibase + ii] = sres[ii * SCRP + o];
    }
}

// ---------------- launch ------------------------------------------------------
extern "C" void kernel_launch(void* const* d_in, const int* in_sizes, int n_in,
                              void* d_out, int out_size) {
    const float* x    = (const float*)d_in[0];   // (8, 64, 4096)
    const float* W    = (const float*)d_in[1];   // (128, 128)
    const float* bvec = (const float*)d_in[2];   // (128,)
    float* out = (float*)d_out;                  // (8, 128, 4096)

    const int SMEM_GEMM = (CC * 256 + CC * 64) * 4;                        // 80KB
    const int SMEM_KNN  = (CC * TI + CC * TJ + TJ + TI * SCRP) * 4
                          + TI * KNN * 4 + TI * KNN * 4;                   // 154112B
    cudaFuncSetAttribute(gemm_gh_kernel, cudaFuncAttributeMaxDynamicSharedMemorySize, SMEM_GEMM);
    cudaFuncSetAttribute(knn_kernel,     cudaFuncAttributeMaxDynamicSharedMemorySize, SMEM_KNN);

    xx_kernel<<<dim3(NN / 256, BB), 256>>>(x);
    uprep_kernel<<<CC, 256>>>(W);
    gemm_gh_kernel<<<dim3(NN / 64, BB), 256, SMEM_GEMM>>>(x, bvec);
    knn_kernel<<<dim3(NN / TI, BB), 256, SMEM_KNN>>>(x);
    gathermax_kernel<<<dim3(NN / 32, BB), 256>>>(out);
}

// round 2
// speedup vs baseline: 1.4427x; 1.4427x over previous
#include <cuda_runtime.h>
#include <cuda_bf16.h>
#include <cstdint>

// Problem constants
#define BB   8
#define CC   64
#define NN   4096
#define OO   128
#define KNN  20

// KNN kernel tiling (2 CTAs/SM version)
#define TI   128      // i rows per block
#define TJ   64       // j cols per chunk
#define SCRP 68       // scr row pitch in floats (68 mod 32 = 4 -> conflict-free)
#define RESP 132      // gathermax result tile pitch

// ---------------- scratch (static device globals; no allocation) -------------
__device__ float g_xx[BB * NN];                 // ||x_j||^2 per point
__device__ float g_Ut[CC * 256];                // combined weights, [c][o'] o'=0..255
__device__ float g_GT[(size_t)BB * NN * OO];    // G^T: [b][j][o], o contiguous
__device__ float g_HT[(size_t)BB * NN * OO];    // H^T: [b][i][o] (incl. bias)
__device__ int   g_idx[(size_t)BB * NN * KNN];  // knn indices

// ---------------- kernel 1: xx[b][j] = sum_c x[b][c][j]^2 --------------------
__global__ void xx_kernel(const float* __restrict__ x) {
    int b = blockIdx.y;
    int j = blockIdx.x * 256 + threadIdx.x;
    const float* xb = x + (size_t)b * CC * NN;
    float acc = 0.f;
#pragma unroll
    for (int c = 0; c < CC; ++c) {
        float v = xb[c * NN + j];
        acc += v * v;
    }
    g_xx[b * NN + j] = acc;
}

// ---------------- kernel 2: build combined weight Ut[c][o'] ------------------
__global__ void uprep_kernel(const float* __restrict__ W) {
    int c = blockIdx.x;          // 0..63
    int o = threadIdx.x;         // 0..255
    float v;
    if (o < OO) v = W[o * (2 * CC) + c];
    else {
        int oo = o - OO;
        v = W[oo * (2 * CC) + CC + c] - W[oo * (2 * CC) + c];
    }
    g_Ut[c * 256 + o] = v;
}

// ---------------- kernel 3: GH^T GEMM -> g_GT / g_HT -------------------------
__global__ __launch_bounds__(256) void gemm_gh_kernel(const float* __restrict__ x,
                                                      const float* __restrict__ bvec) {
    extern __shared__ float sm[];
    float* su = sm;                 // [64][256]
    float* sx = sm + CC * 256;      // [64][64]

    int b = blockIdx.y;
    int jbase = blockIdx.x * 64;
    int t = threadIdx.x;
    int tx = t & 7;                 // j group (8 j's)
    int ty = t >> 3;                // o group (8 o's), 0..31

    const float4* ut4 = (const float4*)g_Ut;
    float4* su4 = (float4*)su;
    for (int k = t; k < CC * 256 / 4; k += 256) su4[k] = ut4[k];

    const float* xb = x + (size_t)b * CC * NN;
    for (int k = t; k < CC * 16; k += 256) {
        int c = k >> 4, p = k & 15;
        float4 v = *(const float4*)&xb[c * NN + jbase + p * 4];
        *(float4*)&sx[c * 64 + p * 4] = v;
    }
    __syncthreads();

    float acc[8][8];
#pragma unroll
    for (int i = 0; i < 8; ++i)
#pragma unroll
        for (int j = 0; j < 8; ++j) acc[i][j] = 0.f;

#pragma unroll 4
    for (int c = 0; c < CC; ++c) {
        float4 a0 = *(float4*)&su[c * 256 + ty * 8];
        float4 a1 = *(float4*)&su[c * 256 + ty * 8 + 4];
        float4 b0 = *(float4*)&sx[c * 64 + tx * 8];
        float4 b1 = *(float4*)&sx[c * 64 + tx * 8 + 4];
        float aa[8] = {a0.x, a0.y, a0.z, a0.w, a1.x, a1.y, a1.z, a1.w};
        float bb[8] = {b0.x, b0.y, b0.z, b0.w, b1.x, b1.y, b1.z, b1.w};
#pragma unroll
        for (int i = 0; i < 8; ++i)
#pragma unroll
            for (int j = 0; j < 8; ++j) acc[i][j] += aa[i] * bb[j];
    }

    int obase = ty * 8;
    bool isH = (obase >= OO);
    float bias[8];
    if (isH) {
#pragma unroll
        for (int i = 0; i < 8; ++i) bias[i] = bvec[obase - OO + i];
    }
#pragma unroll
    for (int jq = 0; jq < 8; ++jq) {
        int j = jbase + tx * 8 + jq;
        float* dst = isH ? &g_HT[((size_t)b * NN + j) * OO + (obase - OO)]
                         : &g_GT[((size_t)b * NN + j) * OO + obase];
#pragma unroll
        for (int i = 0; i < 8; ++i) {
            float v = acc[i][jq];
            if (isH) v += bias[i];
            dst[i] = v;
        }
    }
}

// ---------------- kernel 4: fused distance GEMM + streaming top-20 -----------
// 256 threads, tile TI=128 x TJ=64 per chunk, per-thread 8i x 4j.
// smem ~104.7KB -> 2 CTAs/SM (16 warps), grid 256 = single wave on 148 SMs.
__global__ __launch_bounds__(256, 2) void knn_kernel(const float* __restrict__ x) {
    extern __shared__ float sm[];
    float* si   = sm;                          // [64][128] holds 2*x_i  (32KB)
    float* sj   = si + CC * TI;                // [64][64]              (16KB)
    float* sxxj = sj + CC * TJ;                // [64]
    float* scr  = sxxj + TJ;                   // [128][68]             (34.8KB)
    float* lv   = scr + TI * SCRP;             // [128][20]
    int*   li   = (int*)(lv + TI * KNN);       // [128][20]

    int b = blockIdx.y;
    int ibase = blockIdx.x * TI;
    int t = threadIdx.x;
    int tx = t & 15;                           // j group: 4 j's at tx*4
    int ty = t >> 4;                           // i group: 8 i's at ty*8

    const float* xb = x + (size_t)b * CC * NN;
    const float* xxb = g_xx + b * NN;

    // init top-k lists
    for (int k = t; k < TI * KNN; k += 256) { lv[k] = -3.4e38f; li[k] = 0; }

    // load si = 2 * x(i tile), once
    for (int k = t; k < CC * TI / 4; k += 256) {
        int c = k >> 5, p = k & 31;
        float4 v = *(const float4*)&xb[c * NN + ibase + p * 4];
        v.x *= 2.f; v.y *= 2.f; v.z *= 2.f; v.w *= 2.f;
        *(float4*)&si[c * TI + p * 4] = v;
    }

    for (int jbase = 0; jbase < NN; jbase += TJ) {
        // load j tile (all threads) + xx chunk (threads 128..143, non-merge warps)
        for (int k = t; k < CC * TJ / 4; k += 256) {
            int c = k >> 4, p = k & 15;
            *(float4*)&sj[c * TJ + p * 4] = *(const float4*)&xb[c * NN + jbase + p * 4];
        }
        if (t >= 128 && t < 144) {
            int p = t - 128;
            *(float4*)&sxxj[p * 4] = *(const float4*)&xxb[jbase + p * 4];
        }
        __syncthreads();   // joins loads AND previous chunk's merge

        float acc[8][4];
#pragma unroll
        for (int i = 0; i < 8; ++i)
#pragma unroll
            for (int j = 0; j < 4; ++j) acc[i][j] = 0.f;

#pragma unroll 4
        for (int c = 0; c < CC; ++c) {
            float4 a0 = *(float4*)&si[c * TI + ty * 8];
            float4 a1 = *(float4*)&si[c * TI + ty * 8 + 4];
            float4 b0 = *(float4*)&sj[c * TJ + tx * 4];
            float aa[8] = {a0.x, a0.y, a0.z, a0.w, a1.x, a1.y, a1.z, a1.w};
#pragma unroll
            for (int i = 0; i < 8; ++i) {
                acc[i][0] += aa[i] * b0.x;
                acc[i][1] += aa[i] * b0.y;
                acc[i][2] += aa[i] * b0.z;
                acc[i][3] += aa[i] * b0.w;
            }
        }

        // score = 2*x_i.x_j - xx_j  (si already holds 2x; -xx_i is rank-invariant)
        float4 xx4 = *(float4*)&sxxj[tx * 4];
#pragma unroll
        for (int i = 0; i < 8; ++i) {
            int r = ty * 8 + i;
            float4 s;
            s.x = acc[i][0] - xx4.x;
            s.y = acc[i][1] - xx4.y;
            s.z = acc[i][2] - xx4.z;
            s.w = acc[i][3] - xx4.w;
            *(float4*)&scr[r * SCRP + tx * 4] = s;
        }
        __syncthreads();   // scores visible before merge

        // streaming top-20 merge: thread r owns row r; warps 4-7 go load next sj
        if (t < TI) {
            float* lvr = lv + t * KNN;
            int*   lir = li + t * KNN;
            float thr = lvr[KNN - 1];
            const float* srow = scr + t * SCRP;
#pragma unroll 4
            for (int jj = 0; jj < TJ; jj += 4) {
                float4 v = *(const float4*)&srow[jj];
                float vs[4] = {v.x, v.y, v.z, v.w};
#pragma unroll
                for (int q = 0; q < 4; ++q) {
                    float s = vs[q];
                    if (s > thr) {
                        int p = KNN - 1;
                        while (p > 0 && lvr[p - 1] < s) {
                            lvr[p] = lvr[p - 1];
                            lir[p] = lir[p - 1];
                            --p;
                        }
                        lvr[p] = s;
                        lir[p] = jbase + jj + q;
                        thr = lvr[KNN - 1];
                    }
                }
            }
        }
        // no barrier: merge never touches sj; top-of-loop barrier re-joins
    }
    __syncthreads();

    if (t < TI) {
        int* dst = &g_idx[((size_t)b * NN + ibase + t) * KNN];
#pragma unroll
        for (int k = 0; k < KNN; ++k) dst[k] = li[t * KNN + k];
    }
}

// ---------------- kernel 5: gather-max + leaky + transposed write ------------
__global__ __launch_bounds__(256) void gathermax_kernel(float* __restrict__ out) {
    __shared__ int   sidx[32 * KNN];
    __shared__ float sres[32 * RESP];
    int b = blockIdx.y;
    int ibase = blockIdx.x * 32;
    int t = threadIdx.x;
    int w = t >> 5;    // warp 0..7
    int l = t & 31;    // lane

    for (int k = t; k < 32 * KNN; k += 256)
        sidx[k] = g_idx[((size_t)b * NN + ibase) * KNN + k];
    __syncthreads();

    const float* GTb = g_GT + (size_t)b * NN * OO;
    const float* HTb = g_HT + (size_t)b * NN * OO;

#pragma unroll
    for (int p = 0; p < 4; ++p) {
        int pp = w * 4 + p;                 // local point 0..31
        int i = ibase + pp;
        float4 m = make_float4(-3.4e38f, -3.4e38f, -3.4e38f, -3.4e38f);
#pragma unroll
        for (int k = 0; k < KNN; ++k) {
            int j = sidx[pp * KNN + k];
            float4 g = *(const float4*)&GTb[(size_t)j * OO + l * 4];
            m.x = fmaxf(m.x, g.x); m.y = fmaxf(m.y, g.y);
            m.z = fmaxf(m.z, g.z); m.w = fmaxf(m.w, g.w);
        }
        float4 h = *(const float4*)&HTb[(size_t)i * OO + l * 4];
        float v0 = m.x + h.x, v1 = m.y + h.y, v2 = m.z + h.z, v3 = m.w + h.w;
        v0 = v0 >= 0.f ? v0 : 0.2f * v0;
        v1 = v1 >= 0.f ? v1 : 0.2f * v1;
        v2 = v2 >= 0.f ? v2 : 0.2f * v2;
        v3 = v3 >= 0.f ? v3 : 0.2f * v3;
        *(float4*)&sres[pp * RESP + l * 4] = make_float4(v0, v1, v2, v3);
    }
    __syncthreads();

    float* ob = out + (size_t)b * OO * NN;
    for (int k = t; k < OO * 32; k += 256) {
        int o = k >> 5, ii = k & 31;
        ob[(size_t)o * NN + ibase + ii] = sres[ii * RESP + o];
    }
}

// ---------------- launch ------------------------------------------------------
extern "C" void kernel_launch(void* const* d_in, const int* in_sizes, int n_in,
                              void* d_out, int out_size) {
    const float* x    = (const float*)d_in[0];   // (8, 64, 4096)
    const float* W    = (const float*)d_in[1];   // (128, 128)
    const float* bvec = (const float*)d_in[2];   // (128,)
    float* out = (float*)d_out;                  // (8, 128, 4096)

    const int SMEM_GEMM = (CC * 256 + CC * 64) * 4;                        // 80KB
    const int SMEM_KNN  = (CC * TI + CC * TJ + TJ + TI * SCRP + TI * KNN) * 4
                          + TI * KNN * 4;                                  // 104704B
    cudaFuncSetAttribute(gemm_gh_kernel, cudaFuncAttributeMaxDynamicSharedMemorySize, SMEM_GEMM);
    cudaFuncSetAttribute(knn_kernel,     cudaFuncAttributeMaxDynamicSharedMemorySize, SMEM_KNN);

    xx_kernel<<<dim3(NN / 256, BB), 256>>>(x);
    uprep_kernel<<<CC, 256>>>(W);
    gemm_gh_kernel<<<dim3(NN / 64, BB), 256, SMEM_GEMM>>>(x, bvec);
    knn_kernel<<<dim3(NN / TI, BB), 256, SMEM_KNN>>>(x);
    gathermax_kernel<<<dim3(NN / 32, BB), 256>>>(out);
}

// round 5
// speedup vs baseline: 1.8316x; 1.2696x over previous
#include <cuda_runtime.h>
#include <cuda_bf16.h>
#include <cstdint>

// Problem constants
#define BB   8
#define CC   64
#define NN   4096
#define OO   128
#define KNN  20

#define RESP 132      // gathermax result tile pitch
#define APITCH 72     // bf16 smem tile pitch (144B: 16B-aligned, ldmatrix conflict-free)
#define SCRP 68       // score tile pitch (floats)

// single dynamic-smem symbol shared by all kernels
extern __shared__ char smem_dyn[];

// ---------------- scratch (static device globals; no allocation) -------------
__device__ float g_xx[BB * NN];                         // ||x_j||^2
__device__ float g_Ut[CC * 256];                        // combined weights [c][o']
__device__ float g_GT[(size_t)BB * NN * OO];            // G^T: [b][j][o]
__device__ float g_HT[(size_t)BB * NN * OO];            // H^T: [b][i][o]
__device__ int   g_idx[(size_t)BB * NN * KNN];          // knn indices
__device__ __nv_bfloat16 g_xt_hi[(size_t)BB * NN * CC]; // x^T split hi: [b][j][c]
__device__ __nv_bfloat16 g_xt_lo[(size_t)BB * NN * CC]; // x^T split lo: [b][j][c]

// ---------------- PTX helpers (base ISA only: ldmatrix + mma.sync) -----------
__device__ __forceinline__ uint32_t smem_u32(const void* p) {
    uint32_t a;
    asm("{ .reg .u64 t; cvta.to.shared.u64 t, %1; cvt.u32.u64 %0, t; }" : "=r"(a) : "l"(p));
    return a;
}
__device__ __forceinline__ void ldsm_x4(uint32_t* r, uint32_t addr) {
    asm volatile("ldmatrix.sync.aligned.m8n8.x4.shared.b16 {%0,%1,%2,%3}, [%4];"
                 : "=r"(r[0]), "=r"(r[1]), "=r"(r[2]), "=r"(r[3]) : "r"(addr));
}
__device__ __forceinline__ void ldsm_x2(uint32_t* r, uint32_t addr) {
    asm volatile("ldmatrix.sync.aligned.m8n8.x2.shared.b16 {%0,%1}, [%2];"
                 : "=r"(r[0]), "=r"(r[1]) : "r"(addr));
}
__device__ __forceinline__ void mma16816(float* d, const uint32_t* a, const uint32_t* b) {
    asm volatile("mma.sync.aligned.m16n8k16.row.col.f32.bf16.bf16.f32 "
                 "{%0,%1,%2,%3}, {%4,%5,%6,%7}, {%8,%9}, {%0,%1,%2,%3};"
                 : "+f"(d[0]), "+f"(d[1]), "+f"(d[2]), "+f"(d[3])
                 : "r"(a[0]), "r"(a[1]), "r"(a[2]), "r"(a[3]), "r"(b[0]), "r"(b[1]));
}

// ---------------- kernel 1: transpose + bf16 split + xx ----------------------
__global__ __launch_bounds__(256) void split_kernel(const float* __restrict__ x) {
    __shared__ float tile[64 * 68];
    __shared__ float part[64 * 4];
    int b = blockIdx.y, jbase = blockIdx.x * 64, t = threadIdx.x;
    const float* xb = x + (size_t)b * CC * NN;
    for (int k = t; k < 64 * 16; k += 256) {
        int c = k >> 4, p = k & 15;
        *(float4*)&tile[c * 68 + p * 4] = *(const float4*)&xb[c * NN + jbase + p * 4];
    }
    __syncthreads();
    int jl = t >> 2, g = t & 3;
    __nv_bfloat16 hi[16], lo[16];
    float ss = 0.f;
#pragma unroll
    for (int cc = 0; cc < 16; ++cc) {
        float v = tile[(g * 16 + cc) * 68 + jl];
        ss += v * v;
        __nv_bfloat16 h = __float2bfloat16(v);
        hi[cc] = h;
        lo[cc] = __float2bfloat16(v - __bfloat162float(h));
    }
    part[jl * 4 + g] = ss;
    size_t base = ((size_t)b * NN + jbase + jl) * CC + g * 16;
    *(uint4*)&g_xt_hi[base]     = *(uint4*)&hi[0];
    *(uint4*)&g_xt_hi[base + 8] = *(uint4*)&hi[8];
    *(uint4*)&g_xt_lo[base]     = *(uint4*)&lo[0];
    *(uint4*)&g_xt_lo[base + 8] = *(uint4*)&lo[8];
    __syncthreads();
    if (t < 64)
        g_xx[b * NN + jbase + t] = part[t * 4] + part[t * 4 + 1] + part[t * 4 + 2] + part[t * 4 + 3];
}

// ---------------- kernel 2: build combined weight Ut[c][o'] ------------------
__global__ void uprep_kernel(const float* __restrict__ W) {
    int c = blockIdx.x;
    int o = threadIdx.x;
    float v;
    if (o < OO) v = W[o * (2 * CC) + c];
    else {
        int oo = o - OO;
        v = W[oo * (2 * CC) + CC + c] - W[oo * (2 * CC) + c];
    }
    g_Ut[c * 256 + o] = v;
}

// ---------------- kernel 3: GH^T GEMM -> g_GT / g_HT -------------------------
__global__ __launch_bounds__(256) void gemm_gh_kernel(const float* __restrict__ x,
                                                      const float* __restrict__ bvec) {
    float* sm = (float*)smem_dyn;
    float* su = sm;                 // [64][256]
    float* sx = sm + CC * 256;      // [64][64]

    int b = blockIdx.y;
    int jbase = blockIdx.x * 64;
    int t = threadIdx.x;
    int tx = t & 7;
    int ty = t >> 3;

    const float4* ut4 = (const float4*)g_Ut;
    float4* su4 = (float4*)su;
    for (int k = t; k < CC * 256 / 4; k += 256) su4[k] = ut4[k];

    const float* xb = x + (size_t)b * CC * NN;
    for (int k = t; k < CC * 16; k += 256) {
        int c = k >> 4, p = k & 15;
        *(float4*)&sx[c * 64 + p * 4] = *(const float4*)&xb[c * NN + jbase + p * 4];
    }
    __syncthreads();

    float acc[8][8];
#pragma unroll
    for (int i = 0; i < 8; ++i)
#pragma unroll
        for (int j = 0; j < 8; ++j) acc[i][j] = 0.f;

#pragma unroll 4
    for (int c = 0; c < CC; ++c) {
        float4 a0 = *(float4*)&su[c * 256 + ty * 8];
        float4 a1 = *(float4*)&su[c * 256 + ty * 8 + 4];
        float4 b0 = *(float4*)&sx[c * 64 + tx * 8];
        float4 b1 = *(float4*)&sx[c * 64 + tx * 8 + 4];
        float aa[8] = {a0.x, a0.y, a0.z, a0.w, a1.x, a1.y, a1.z, a1.w};
        float bb[8] = {b0.x, b0.y, b0.z, b0.w, b1.x, b1.y, b1.z, b1.w};
#pragma unroll
        for (int i = 0; i < 8; ++i)
#pragma unroll
            for (int j = 0; j < 8; ++j) acc[i][j] += aa[i] * bb[j];
    }

    int obase = ty * 8;
    bool isH = (obase >= OO);
    float bias[8];
    if (isH) {
#pragma unroll
        for (int i = 0; i < 8; ++i) bias[i] = bvec[obase - OO + i];
    }
#pragma unroll
    for (int jq = 0; jq < 8; ++jq) {
        int j = jbase + tx * 8 + jq;
        float* dst = isH ? &g_HT[((size_t)b * NN + j) * OO + (obase - OO)]
                         : &g_GT[((size_t)b * NN + j) * OO + obase];
#pragma unroll
        for (int i = 0; i < 8; ++i) {
            float v = acc[i][jq];
            if (isH) v += bias[i];
            dst[i] = v;
        }
    }
}

// ---------------- kernel 4: HMMA distance GEMM + streaming top-20 ------------
// 128 threads (4 warps). TI=128 i rows, j streamed in chunks of 64.
// dot = Ahi.Bhi + Ahi.Blo + Alo.Bhi (bf16 split, fp32 accum).
// smem offsets (bytes):
#define OFF_AHI  0
#define OFF_ALO  (OFF_AHI + 128 * APITCH * 2)   // 18432
#define OFF_BHI  (OFF_ALO + 128 * APITCH * 2)   // 36864
#define OFF_BLO  (OFF_BHI + 64 * APITCH * 2)    // 46080
#define OFF_SCR  (OFF_BLO + 64 * APITCH * 2)    // 55296
#define OFF_NXX  (OFF_SCR + 128 * SCRP * 4)     // 90112
#define OFF_LV   (OFF_NXX + 64 * 4)             // 90368
#define OFF_LI   (OFF_LV + 128 * KNN * 4)       // 100608
#define KNN_SMEM (OFF_LI + 128 * KNN * 4)       // 110848 bytes

__global__ __launch_bounds__(128) void knn_kernel() {
    char* sm = smem_dyn;
    uint32_t sbase = smem_u32(sm);
    int t = threadIdx.x;
    int warp = t >> 5, lane = t & 31;
    int b = blockIdx.y;
    int ibase = blockIdx.x * 128;

    __nv_bfloat16* sAhi = (__nv_bfloat16*)(sm + OFF_AHI);
    __nv_bfloat16* sAlo = (__nv_bfloat16*)(sm + OFF_ALO);
    __nv_bfloat16* sBhi = (__nv_bfloat16*)(sm + OFF_BHI);
    __nv_bfloat16* sBlo = (__nv_bfloat16*)(sm + OFF_BLO);
    float* scr = (float*)(sm + OFF_SCR);
    float* nxx = (float*)(sm + OFF_NXX);
    float* lv  = (float*)(sm + OFF_LV);
    int*   li  = (int*)(sm + OFF_LI);

    // init top-k lists
    for (int k = t; k < 128 * KNN; k += 128) { lv[k] = -3.4e38f; li[k] = 0; }

    // load A tiles (hi/lo), pitch APITCH
    {
        const uint4* srcH = (const uint4*)(g_xt_hi + ((size_t)b * NN + ibase) * CC);
        const uint4* srcL = (const uint4*)(g_xt_lo + ((size_t)b * NN + ibase) * CC);
#pragma unroll
        for (int it = 0; it < 8; ++it) {
            int k = t + it * 128;          // 16B chunk id: row=k>>3, p=k&7
            int row = k >> 3, p = k & 7;
            *(uint4*)&sAhi[row * APITCH + p * 8] = srcH[k];
            *(uint4*)&sAlo[row * APITCH + p * 8] = srcL[k];
        }
    }

    const float* xxb = g_xx + b * NN;
    float thr = -3.4e38f;
    float* lvr = lv + t * KNN;
    int*   lir = li + t * KNN;
    int mrow0 = warp * 32;

    for (int jbase = 0; jbase < NN; jbase += 64) {
        // load B tiles (64 rows x 64 bf16, hi+lo) + negated xx chunk
        const uint4* srcH = (const uint4*)(g_xt_hi + ((size_t)b * NN + jbase) * CC);
        const uint4* srcL = (const uint4*)(g_xt_lo + ((size_t)b * NN + jbase) * CC);
#pragma unroll
        for (int it = 0; it < 4; ++it) {
            int k = t + it * 128;          // 512 chunks total
            int row = k >> 3, p = k & 7;
            *(uint4*)&sBhi[row * APITCH + p * 8] = srcH[k];
            *(uint4*)&sBlo[row * APITCH + p * 8] = srcL[k];
        }
        if (t < 16) {
            float4 v = *(const float4*)&xxb[jbase + t * 4];
            v.x = -v.x; v.y = -v.y; v.z = -v.z; v.w = -v.w;
            *(float4*)&nxx[t * 4] = v;
        }
        __syncthreads();   // B ready; also joins previous chunk's scan

        float acc[2][8][4];
#pragma unroll
        for (int mi = 0; mi < 2; ++mi)
#pragma unroll
            for (int nj = 0; nj < 8; ++nj)
#pragma unroll
                for (int q = 0; q < 4; ++q) acc[mi][nj][q] = 0.f;

        // ldmatrix lane address components
        int arow = (lane & 7) + 8 * ((lane >> 3) & 1);
        int asel = 8 * (lane >> 4);
        int brow = lane & 7;
        int bsel = 8 * ((lane >> 3) & 1);

#pragma unroll
        for (int ks = 0; ks < 4; ++ks) {
            int kc = ks * 16;
            uint32_t ah[2][4], al[2][4], bh[8][2], bl[8][2];
#pragma unroll
            for (int mi = 0; mi < 2; ++mi) {
                uint32_t off = ((mrow0 + mi * 16 + arow) * APITCH + kc + asel) * 2;
                ldsm_x4(ah[mi], sbase + OFF_AHI + off);
                ldsm_x4(al[mi], sbase + OFF_ALO + off);
            }
#pragma unroll
            for (int nj = 0; nj < 8; ++nj) {
                uint32_t off = ((nj * 8 + brow) * APITCH + kc + bsel) * 2;
                ldsm_x2(bh[nj], sbase + OFF_BHI + off);
                ldsm_x2(bl[nj], sbase + OFF_BLO + off);
            }
#pragma unroll
            for (int mi = 0; mi < 2; ++mi)
#pragma unroll
                for (int nj = 0; nj < 8; ++nj) {
                    mma16816(acc[mi][nj], ah[mi], bh[nj]);
                    mma16816(acc[mi][nj], ah[mi], bl[nj]);
                    mma16816(acc[mi][nj], al[mi], bh[nj]);
                }
        }

        // write D fragments to scr
        int gid = lane >> 2, tig = lane & 3;
#pragma unroll
        for (int mi = 0; mi < 2; ++mi) {
            int r = mrow0 + mi * 16 + gid;
#pragma unroll
            for (int nj = 0; nj < 8; ++nj) {
                int jc = nj * 8 + tig * 2;
                *(float2*)&scr[r * SCRP + jc]       = make_float2(acc[mi][nj][0], acc[mi][nj][1]);
                *(float2*)&scr[(r + 8) * SCRP + jc] = make_float2(acc[mi][nj][2], acc[mi][nj][3]);
            }
        }
        __syncthreads();   // scores visible

        // streaming top-20: thread t owns row t
        {
            const float* srow = scr + t * SCRP;
#pragma unroll 4
            for (int jj = 0; jj < 64; jj += 4) {
                float4 d = *(const float4*)&srow[jj];
                float4 nx = *(const float4*)&nxx[jj];
                float vs[4];
                vs[0] = fmaf(2.f, d.x, nx.x);
                vs[1] = fmaf(2.f, d.y, nx.y);
                vs[2] = fmaf(2.f, d.z, nx.z);
                vs[3] = fmaf(2.f, d.w, nx.w);
#pragma unroll
                for (int q = 0; q < 4; ++q) {
                    float s = vs[q];
                    if (s > thr) {
                        int p = KNN - 1;
                        while (p > 0 && lvr[p - 1] < s) {
                            lvr[p] = lvr[p - 1];
                            lir[p] = lir[p - 1];
                            --p;
                        }
                        lvr[p] = s;
                        lir[p] = jbase + jj + q;
                        thr = lvr[KNN - 1];
                    }
                }
            }
        }
        __syncthreads();   // scan done before scr/B overwritten
    }

    int* dst = &g_idx[((size_t)b * NN + ibase + t) * KNN];
#pragma unroll
    for (int k = 0; k < KNN; ++k) dst[k] = lir[k];
}

// ---------------- kernel 5: gather-max + leaky + transposed write ------------
__global__ __launch_bounds__(256) void gathermax_kernel(float* __restrict__ out) {
    __shared__ int   sidx[32 * KNN];
    __shared__ float sres[32 * RESP];
    int b = blockIdx.y;
    int ibase = blockIdx.x * 32;
    int t = threadIdx.x;
    int w = t >> 5;
    int l = t & 31;

    for (int k = t; k < 32 * KNN; k += 256)
        sidx[k] = g_idx[((size_t)b * NN + ibase) * KNN + k];
    __syncthreads();

    const float* GTb = g_GT + (size_t)b * NN * OO;
    const float* HTb = g_HT + (size_t)b * NN * OO;

#pragma unroll
    for (int p = 0; p < 4; ++p) {
        int pp = w * 4 + p;
        int i = ibase + pp;
        float4 m = make_float4(-3.4e38f, -3.4e38f, -3.4e38f, -3.4e38f);
#pragma unroll
        for (int k = 0; k < KNN; ++k) {
            int j = sidx[pp * KNN + k];
            float4 g = *(const float4*)&GTb[(size_t)j * OO + l * 4];
            m.x = fmaxf(m.x, g.x); m.y = fmaxf(m.y, g.y);
            m.z = fmaxf(m.z, g.z); m.w = fmaxf(m.w, g.w);
        }
        float4 h = *(const float4*)&HTb[(size_t)i * OO + l * 4];
        float v0 = m.x + h.x, v1 = m.y + h.y, v2 = m.z + h.z, v3 = m.w + h.w;
        v0 = v0 >= 0.f ? v0 : 0.2f * v0;
        v1 = v1 >= 0.f ? v1 : 0.2f * v1;
        v2 = v2 >= 0.f ? v2 : 0.2f * v2;
        v3 = v3 >= 0.f ? v3 : 0.2f * v3;
        *(float4*)&sres[pp * RESP + l * 4] = make_float4(v0, v1, v2, v3);
    }
    __syncthreads();

    float* ob = out + (size_t)b * OO * NN;
    for (int k = t; k < OO * 32; k += 256) {
        int o = k >> 5, ii = k & 31;
        ob[(size_t)o * NN + ibase + ii] = sres[ii * RESP + o];
    }
}

// ---------------- launch ------------------------------------------------------
extern "C" void kernel_launch(void* const* d_in, const int* in_sizes, int n_in,
                              void* d_out, int out_size) {
    const float* x    = (const float*)d_in[0];   // (8, 64, 4096)
    const float* W    = (const float*)d_in[1];   // (128, 128)
    const float* bvec = (const float*)d_in[2];   // (128,)
    float* out = (float*)d_out;                  // (8, 128, 4096)

    const int SMEM_GEMM = (CC * 256 + CC * 64) * 4;   // 80KB
    cudaFuncSetAttribute(gemm_gh_kernel, cudaFuncAttributeMaxDynamicSharedMemorySize, SMEM_GEMM);
    cudaFuncSetAttribute(knn_kernel,     cudaFuncAttributeMaxDynamicSharedMemorySize, KNN_SMEM);

    split_kernel<<<dim3(NN / 64, BB), 256>>>(x);
    uprep_kernel<<<CC, 256>>>(W);
    gemm_gh_kernel<<<dim3(NN / 64, BB), 256, SMEM_GEMM>>>(x, bvec);
    knn_kernel<<<dim3(NN / 128, BB), 128, KNN_SMEM>>>();
    gathermax_kernel<<<dim3(NN / 32, BB), 256>>>(out);
}